// round 16
// baseline (speedup 1.0000x reference)
#include <cuda_runtime.h>
#include <cuda_bf16.h>
#include <cstdint>

// Problem constants (fixed by the dataset)
#define M_MAX   8192
#define K_DIM   4096
#define N_DIM   4096
#define NBASIS  256

// Scratch (static device arrays — no allocation allowed)
__device__ __nv_bfloat16 g_Xhi[M_MAX * K_DIM];
__device__ __nv_bfloat16 g_Xlo[M_MAX * K_DIM];
__device__ __nv_bfloat16 g_Wres[N_DIM * K_DIM];
__device__ __nv_bfloat16 g_Bhi[NBASIS * K_DIM];
__device__ __nv_bfloat16 g_Blo[NBASIS * K_DIM];
__device__ float         g_Pt [NBASIS * M_MAX];  // Pt[basis][m]
__device__ int           g_flagP;                // # of completed P tiles

// ---------------------------------------------------------------------------
// Prep kernels
// ---------------------------------------------------------------------------

__global__ void prep_x(const float* __restrict__ x,
                       __nv_bfloat16* __restrict__ hi,
                       __nv_bfloat16* __restrict__ lo, int n4) {
    int i = blockIdx.x * blockDim.x + threadIdx.x;
    if (i >= n4) return;
    float4 v = ((const float4*)x)[i];
    __nv_bfloat162 h01 = __floats2bfloat162_rn(v.x, v.y);
    __nv_bfloat162 h23 = __floats2bfloat162_rn(v.z, v.w);
    ((__nv_bfloat162*)hi)[2 * i]     = h01;
    ((__nv_bfloat162*)hi)[2 * i + 1] = h23;
    float l0 = v.x - __bfloat162float(h01.x);
    float l1 = v.y - __bfloat162float(h01.y);
    float l2 = v.z - __bfloat162float(h23.x);
    float l3 = v.w - __bfloat162float(h23.y);
    ((__nv_bfloat162*)lo)[2 * i]     = __floats2bfloat162_rn(l0, l1);
    ((__nv_bfloat162*)lo)[2 * i + 1] = __floats2bfloat162_rn(l2, l3);
}

__global__ void prep_w(const int* __restrict__ q,
                       __nv_bfloat16* __restrict__ w, int n4) {
    int i = blockIdx.x * blockDim.x + threadIdx.x;
    if (i == 0) g_flagP = 0;            // reset P-completion flag every launch
    if (i >= n4) return;
    int4 v = ((const int4*)q)[i];
    // q - 128 is an integer in [-128,127]: exactly representable in bf16.
    __nv_bfloat162 w01 = __floats2bfloat162_rn((float)(v.x - 128), (float)(v.y - 128));
    __nv_bfloat162 w23 = __floats2bfloat162_rn((float)(v.z - 128), (float)(v.w - 128));
    ((__nv_bfloat162*)w)[2 * i]     = w01;
    ((__nv_bfloat162*)w)[2 * i + 1] = w23;
}

// ---------------------------------------------------------------------------
// MMA helpers (legacy HMMA pipe: ldmatrix + mma.sync.m16n8k16.bf16 + cp.async)
// ---------------------------------------------------------------------------

__device__ __forceinline__ void ldsm4(uint32_t& r0, uint32_t& r1,
                                      uint32_t& r2, uint32_t& r3, uint32_t a) {
    asm volatile("ldmatrix.sync.aligned.m8n8.x4.shared.b16 {%0,%1,%2,%3}, [%4];"
                 : "=r"(r0), "=r"(r1), "=r"(r2), "=r"(r3) : "r"(a));
}

__device__ __forceinline__ void mma16(float* c, const uint32_t* a, const uint32_t* b) {
    asm volatile(
        "mma.sync.aligned.m16n8k16.row.col.f32.bf16.bf16.f32 "
        "{%0,%1,%2,%3},{%4,%5,%6,%7},{%8,%9},{%0,%1,%2,%3};"
        : "+f"(c[0]), "+f"(c[1]), "+f"(c[2]), "+f"(c[3])
        : "r"(a[0]), "r"(a[1]), "r"(a[2]), "r"(a[3]), "r"(b[0]), "r"(b[1]));
}

__device__ __forceinline__ void cp16(uint32_t s, const void* g) {
    asm volatile("cp.async.cg.shared.global [%0], [%1], 16;" :: "r"(s), "l"(g));
}

#define ASTR 144   // 128B of K (64 bf16) + 16B pad: conflict-free ldmatrix phases

// Fragment loaders. a4: 4 m16-frags (64 rows); a2: 2 m16-frags (32 rows);
// b8: 8 n8-frags (64 rows) loaded pairwise via ldsm.x4.
__device__ __forceinline__ void ldfragsA4(uint32_t (*a)[4], uint32_t Ab, int rowBase,
                                          int kb, int lg, int li) {
#pragma unroll
    for (int mt = 0; mt < 4; mt++) {
        int row = rowBase + mt * 16 + li + (lg & 1) * 8;
        ldsm4(a[mt][0], a[mt][1], a[mt][2], a[mt][3],
              Ab + row * ASTR + kb + (lg >> 1) * 16);
    }
}
__device__ __forceinline__ void ldfragsA2(uint32_t (*a)[4], uint32_t Ab, int rowBase,
                                          int kb, int lg, int li) {
#pragma unroll
    for (int mt = 0; mt < 2; mt++) {
        int row = rowBase + mt * 16 + li + (lg & 1) * 8;
        ldsm4(a[mt][0], a[mt][1], a[mt][2], a[mt][3],
              Ab + row * ASTR + kb + (lg >> 1) * 16);
    }
}
__device__ __forceinline__ void ldfragsB8(uint32_t (*b)[2], uint32_t Bb, int rowBase,
                                          int kb, int lg, int li) {
#pragma unroll
    for (int g = 0; g < 4; g++) {
        int row = rowBase + g * 16 + li + (lg >> 1) * 8;
        uint32_t r0, r1, r2, r3;
        ldsm4(r0, r1, r2, r3, Bb + row * ASTR + kb + (lg & 1) * 16);
        b[2 * g][0] = r0; b[2 * g][1] = r1;
        b[2 * g + 1][0] = r2; b[2 * g + 1][1] = r3;
    }
}

// ---------------------------------------------------------------------------
// MERGED kernel: P tiles and big-GEMM tiles in ONE launch, interleaved bids.
//   even bid in [0,512)  -> P tile  p = bid/2   (256 tiles, 64x128)
//   odd  bid in [0,512)  -> big tile t = bid/2  (tiles 0..255)
//   bid in [512, 2304)   -> big tile t = bid-256 (tiles 256..2047)
// Wave 1 (296 slots at 2 CTAs/SM) thus holds 148 P + 148 big CTAs: P always
// makes progress, so the flag spin in big epilogues cannot deadlock.
//
// P body (R12):   Pt[b][m] = Bhi.Xhi + Blo.Xhi + Bhi.Xlo  (fused 3-product)
// big body (R12): acc = Xhi[m].Wres[o]; epilogue waits for all 256 P tiles,
//                 then y = sp*acc + r*Pt[idx][m] + bias.
// ---------------------------------------------------------------------------

__global__ __launch_bounds__(128, 2)
void gemm_merged(const __nv_bfloat16* __restrict__ Bh, const __nv_bfloat16* __restrict__ Bl,
                 const __nv_bfloat16* __restrict__ Xh, const __nv_bfloat16* __restrict__ Xl,
                 const __nv_bfloat16* __restrict__ W,
                 float* __restrict__ Y, float* __restrict__ Pt,
                 const int* __restrict__ codes, const float* __restrict__ scales,
                 const float* __restrict__ bias, int N, int Mtot)
{
    extern __shared__ char smem[];
    const int tid = threadIdx.x, lane = tid & 31, wid = tid >> 5;
    const uint32_t sb = (uint32_t)__cvta_generic_to_shared(smem);
    const int lg = lane >> 3, li = lane & 7;
    const int bid = blockIdx.x;
    const bool isP = (bid < 512) && ((bid & 1) == 0);

    if (isP) {
        // ----------------- P tile (R12 fused 3-product body) -----------------
        constexpr int BA = 64, BT = 128;
        constexpr int OFF_AHI = 0;
        constexpr int OFF_ALO = BA * ASTR;
        constexpr int OFF_XHI = 2 * BA * ASTR;
        constexpr int OFF_XLO = OFF_XHI + BT * ASTR;
        constexpr int STAGE   = OFF_XLO + BT * ASTR;   // 55296
        const int p = bid >> 1;
        const size_t aBase = (size_t)(p >> 6) * BA;    // basis dim (0..3)
        const size_t nBase = (size_t)(p & 63) * BT;    // token dim (0..63)
        const int wm = wid & 1, wn = wid >> 1;
        const int aRow = wm * 32, bRow = wn * 64;

        float acc[2][8][4];
#pragma unroll
        for (int i = 0; i < 2; i++)
#pragma unroll
            for (int j = 0; j < 8; j++)
#pragma unroll
                for (int k = 0; k < 4; k++) acc[i][j][k] = 0.f;

        auto fill = [&](int s, int kt) {
            size_t koff = (size_t)kt * 64;
            uint32_t base = sb + s * STAGE;
#pragma unroll
            for (int i = 0; i < 24; i++) {
                int id = tid + i * 128;
                int c = id & 7;
                const __nv_bfloat16* src;
                uint32_t dst;
                if (id < 512) {
                    int rr = id >> 3;
                    src = Bh + (aBase + rr) * (size_t)K_DIM;
                    dst = base + OFF_AHI + rr * ASTR;
                } else if (id < 1024) {
                    int rr = (id - 512) >> 3;
                    src = Bl + (aBase + rr) * (size_t)K_DIM;
                    dst = base + OFF_ALO + rr * ASTR;
                } else if (id < 2048) {
                    int rr = (id - 1024) >> 3;
                    src = Xh + (nBase + rr) * (size_t)K_DIM;
                    dst = base + OFF_XHI + rr * ASTR;
                } else {
                    int rr = (id - 2048) >> 3;
                    src = Xl + (nBase + rr) * (size_t)K_DIM;
                    dst = base + OFF_XLO + rr * ASTR;
                }
                cp16(dst + c * 16, src + koff + c * 8);
            }
            asm volatile("cp.async.commit_group;" ::: "memory");
        };

        fill(0, 0);
        fill(1, 1);
        const int KT = K_DIM / 64;   // 64

        for (int kt = 0; kt < KT; kt++) {
            int s = kt & 1;
            asm volatile("cp.async.wait_group 1;" ::: "memory");
            __syncthreads();

            uint32_t Ah  = sb + s * STAGE + OFF_AHI;
            uint32_t Al  = sb + s * STAGE + OFF_ALO;
            uint32_t Xhb = sb + s * STAGE + OFF_XHI;
            uint32_t Xlb = sb + s * STAGE + OFF_XLO;

            uint32_t ah[2][2][4], al[2][2][4], xh[2][8][2], xl[2][8][2];
            ldfragsA2(ah[0], Ah, aRow, 0, lg, li);
            ldfragsA2(al[0], Al, aRow, 0, lg, li);
            ldfragsB8(xh[0], Xhb, bRow, 0, lg, li);
            ldfragsB8(xl[0], Xlb, bRow, 0, lg, li);
#pragma unroll
            for (int k16 = 0; k16 < 4; k16++) {
                int cur = k16 & 1, nxt = cur ^ 1;
                if (k16 < 3) {
                    int kb = (k16 + 1) * 32;
                    ldfragsA2(ah[nxt], Ah, aRow, kb, lg, li);
                    ldfragsA2(al[nxt], Al, aRow, kb, lg, li);
                    ldfragsB8(xh[nxt], Xhb, bRow, kb, lg, li);
                    ldfragsB8(xl[nxt], Xlb, bRow, kb, lg, li);
                }
#pragma unroll
                for (int mt = 0; mt < 2; mt++)
#pragma unroll
                    for (int nt = 0; nt < 8; nt++) {
                        mma16(acc[mt][nt], ah[cur][mt], xh[cur][nt]);  // hi.hi
                        mma16(acc[mt][nt], al[cur][mt], xh[cur][nt]);  // lo.hi
                        mma16(acc[mt][nt], ah[cur][mt], xl[cur][nt]);  // hi.lo
                    }
            }
            __syncthreads();
            if (kt + 2 < KT) fill(s, kt + 2);
            else asm volatile("cp.async.commit_group;" ::: "memory");
        }
        asm volatile("cp.async.wait_group 0;" ::: "memory");
        __syncthreads();

        const int t4 = lane >> 2, t2 = (lane & 3) * 2;
#pragma unroll
        for (int mt = 0; mt < 2; mt++) {
#pragma unroll
            for (int pp = 0; pp < 2; pp++) {
                size_t bg = aBase + wm * 32 + mt * 16 + t4 + pp * 8;
#pragma unroll
                for (int nt = 0; nt < 8; nt++) {
                    size_t mcol = nBase + wn * 64 + nt * 8 + t2;
                    *(float2*)(Pt + bg * (size_t)Mtot + mcol) =
                        make_float2(acc[mt][nt][2 * pp + 0], acc[mt][nt][2 * pp + 1]);
                }
            }
        }
        // Publish completion: all stores fenced to device scope, then count.
        __threadfence();
        __syncthreads();
        if (tid == 0) atomicAdd(&g_flagP, 1);
    } else {
        // ----------------- big tile (R12 128x128 3-stage body) ---------------
        constexpr int BM = 128, BN = 128;
        constexpr int STAGE = (BM + BN) * ASTR;    // 36864
        constexpr int OFF_ST = 2048;
        const int t = (bid < 512) ? (bid >> 1) : (bid - 256);
        const size_t mBase = (size_t)(t >> 5) * BM;    // 0..63
        const size_t nBase = (size_t)(t & 31) * BN;    // 0..31
        const int wm = wid & 1, wn = wid >> 1;
        const int aRow = wm * 64, bRow = wn * 64;

        int*   idx_s = (int*)smem;
        float* r_s   = (float*)smem + BN;
        float* sp_s  = (float*)smem + 2 * BN;
        float* b_s   = (float*)smem + 3 * BN;
        if (tid < BN) {
            int c = tid;
            int code = codes[nBase + c];
            idx_s[c] = code & 0xFF;
            r_s[c]   = (float)((code >> 8) & 0xFFFF) * (1.0f / 65535.0f);
            sp_s[c]  = scales[nBase + c] * (1.0f / 127.0f);
            b_s[c]   = bias[nBase + c];
        }

        float acc[4][8][4];
#pragma unroll
        for (int i = 0; i < 4; i++)
#pragma unroll
            for (int j = 0; j < 8; j++)
#pragma unroll
                for (int k = 0; k < 4; k++) acc[i][j][k] = 0.f;

        auto fill = [&](int s, int kt) {
            size_t koff = (size_t)kt * 64;
            uint32_t base = sb + OFF_ST + s * STAGE;
#pragma unroll
            for (int i = 0; i < 16; i++) {
                int id = tid + i * 128;
                bool isB = id >= BM * 8;
                int li2 = isB ? id - BM * 8 : id;
                int r = li2 >> 3, c = li2 & 7;
                const __nv_bfloat16* src =
                    (isB ? W + (nBase + r) * (size_t)K_DIM
                         : Xh + (mBase + r) * (size_t)K_DIM) + koff + c * 8;
                cp16(base + (isB ? BM * ASTR : 0) + r * ASTR + c * 16, src);
            }
            asm volatile("cp.async.commit_group;" ::: "memory");
        };

        fill(0, 0);
        fill(1, 1);
        const int KT = K_DIM / 64;   // 64

        for (int kt = 0; kt < KT; kt++) {
            int s = kt % 3;
            asm volatile("cp.async.wait_group 1;" ::: "memory");
            __syncthreads();
            if (kt + 2 < KT) fill((kt + 2) % 3, kt + 2);
            else asm volatile("cp.async.commit_group;" ::: "memory");

            uint32_t Ab = sb + OFF_ST + s * STAGE;
            uint32_t Bb = Ab + BM * ASTR;

            uint32_t a[2][4][4], b[2][8][2];
            ldfragsA4(a[0], Ab, aRow, 0, lg, li);
            ldfragsB8(b[0], Bb, bRow, 0, lg, li);
#pragma unroll
            for (int k16 = 0; k16 < 4; k16++) {
                int cur = k16 & 1, nxt = cur ^ 1;
                if (k16 < 3) {
                    ldfragsA4(a[nxt], Ab, aRow, (k16 + 1) * 32, lg, li);
                    ldfragsB8(b[nxt], Bb, bRow, (k16 + 1) * 32, lg, li);
                }
#pragma unroll
                for (int mt = 0; mt < 4; mt++)
#pragma unroll
                    for (int nt = 0; nt < 8; nt++)
                        mma16(acc[mt][nt], a[cur][mt], b[cur][nt]);
            }
        }
        asm volatile("cp.async.wait_group 0;" ::: "memory");
        __syncthreads();

        // Wait for ALL 256 P tiles before reading Pt in the epilogue.
        if (tid == 0) {
            while (atomicAdd(&g_flagP, 0) < 256) __nanosleep(256);
        }
        __syncthreads();
        __threadfence();

        const int t4 = lane >> 2, t2 = (lane & 3) * 2;
#pragma unroll
        for (int mt = 0; mt < 4; mt++) {
#pragma unroll
            for (int pp = 0; pp < 2; pp++) {
                size_t m = mBase + wm * 64 + mt * 16 + t4 + pp * 8;
#pragma unroll
                for (int nt = 0; nt < 8; nt++) {
                    int nl = wn * 64 + nt * 8 + t2;
                    size_t n = nBase + nl;
                    float v0 = fmaf(sp_s[nl], acc[mt][nt][2 * pp + 0],
                               fmaf(r_s[nl],
                                    __ldg(&Pt[(size_t)idx_s[nl] * Mtot + m]), b_s[nl]));
                    float v1 = fmaf(sp_s[nl + 1], acc[mt][nt][2 * pp + 1],
                               fmaf(r_s[nl + 1],
                                    __ldg(&Pt[(size_t)idx_s[nl + 1] * Mtot + m]), b_s[nl + 1]));
                    *(float2*)(Y + m * (size_t)N + n) = make_float2(v0, v1);
                }
            }
        }
    }
}

// ---------------------------------------------------------------------------
// Launch
// ---------------------------------------------------------------------------

extern "C" void kernel_launch(void* const* d_in, const int* in_sizes, int n_in,
                              void* d_out, int out_size) {
    const float* x      = (const float*)d_in[0];
    const int*   codes  = (const int*)d_in[1];
    const float* basis  = (const float*)d_in[2];
    const int*   residq = (const int*)d_in[3];
    const float* scales = (const float*)d_in[4];
    const float* bias   = (const float*)d_in[5];
    float*       y      = (float*)d_out;

    int N = in_sizes[1];                 // 4096
    int K = in_sizes[2] / NBASIS;        // 4096
    int M = in_sizes[0] / K;             // 8192

    __nv_bfloat16 *Xhi, *Xlo, *Wres, *Bhi, *Blo;
    float* Pt;
    cudaGetSymbolAddress((void**)&Xhi,  g_Xhi);
    cudaGetSymbolAddress((void**)&Xlo,  g_Xlo);
    cudaGetSymbolAddress((void**)&Wres, g_Wres);
    cudaGetSymbolAddress((void**)&Bhi,  g_Bhi);
    cudaGetSymbolAddress((void**)&Blo,  g_Blo);
    cudaGetSymbolAddress((void**)&Pt,   g_Pt);

    // Unified smem: max(P body 110592, big body 2048 + 3*36864 = 112640)
    constexpr int SMEM_MERGED = 2048 + 3 * (128 + 128) * ASTR;   // 112640
    cudaFuncSetAttribute(gemm_merged,
                         cudaFuncAttributeMaxDynamicSharedMemorySize, SMEM_MERGED);

    // 1) Preprocess (prep_w also resets the P-completion flag)
    int nx4 = (M * K) / 4;
    prep_x<<<(nx4 + 255) / 256, 256>>>(x, Xhi, Xlo, nx4);
    int nb4 = (NBASIS * K) / 4;
    prep_x<<<(nb4 + 255) / 256, 256>>>(basis, Bhi, Blo, nb4);
    int nw4 = (N * K) / 4;
    prep_w<<<(nw4 + 255) / 256, 256>>>(residq, Wres, nw4);

    // 2) Merged P + big GEMM launch (interleaved bids; P overlaps big mainloop)
    //    grid = 256 P tiles + 2048 big tiles = 2304 CTAs
    gemm_merged<<<2304, 128, SMEM_MERGED>>>(
        Bhi, Blo, Xhi, Xlo, Wres, y, Pt, codes, scales, bias, N, M);
}

// round 17
// speedup vs baseline: 1.3257x; 1.3257x over previous
#include <cuda_runtime.h>
#include <cuda_bf16.h>
#include <cstdint>

// Problem constants (fixed by the dataset)
#define M_MAX   8192
#define K_DIM   4096
#define N_DIM   4096
#define NBASIS  256

// Scratch (static device arrays — no allocation allowed)
__device__ __nv_bfloat16 g_Xhi[M_MAX * K_DIM];
__device__ __nv_bfloat16 g_Xlo[M_MAX * K_DIM];
__device__ __nv_bfloat16 g_Wres[N_DIM * K_DIM];
__device__ __nv_bfloat16 g_Bhi[NBASIS * K_DIM];
__device__ __nv_bfloat16 g_Blo[NBASIS * K_DIM];
__device__ float         g_Pt [NBASIS * M_MAX];  // Pt[basis][m]

// ---------------------------------------------------------------------------
// Prep kernels (unchanged from R12)
// ---------------------------------------------------------------------------

__global__ void prep_x(const float* __restrict__ x,
                       __nv_bfloat16* __restrict__ hi,
                       __nv_bfloat16* __restrict__ lo, int n4) {
    int i = blockIdx.x * blockDim.x + threadIdx.x;
    if (i >= n4) return;
    float4 v = ((const float4*)x)[i];
    __nv_bfloat162 h01 = __floats2bfloat162_rn(v.x, v.y);
    __nv_bfloat162 h23 = __floats2bfloat162_rn(v.z, v.w);
    ((__nv_bfloat162*)hi)[2 * i]     = h01;
    ((__nv_bfloat162*)hi)[2 * i + 1] = h23;
    float l0 = v.x - __bfloat162float(h01.x);
    float l1 = v.y - __bfloat162float(h01.y);
    float l2 = v.z - __bfloat162float(h23.x);
    float l3 = v.w - __bfloat162float(h23.y);
    ((__nv_bfloat162*)lo)[2 * i]     = __floats2bfloat162_rn(l0, l1);
    ((__nv_bfloat162*)lo)[2 * i + 1] = __floats2bfloat162_rn(l2, l3);
}

__global__ void prep_w(const int* __restrict__ q,
                       __nv_bfloat16* __restrict__ w, int n4) {
    int i = blockIdx.x * blockDim.x + threadIdx.x;
    if (i >= n4) return;
    int4 v = ((const int4*)q)[i];
    // q - 128 is an integer in [-128,127]: exactly representable in bf16.
    __nv_bfloat162 w01 = __floats2bfloat162_rn((float)(v.x - 128), (float)(v.y - 128));
    __nv_bfloat162 w23 = __floats2bfloat162_rn((float)(v.z - 128), (float)(v.w - 128));
    ((__nv_bfloat162*)w)[2 * i]     = w01;
    ((__nv_bfloat162*)w)[2 * i + 1] = w23;
}

// ---------------------------------------------------------------------------
// MMA helpers (legacy HMMA pipe: ldmatrix + mma.sync.m16n8k16.bf16 + cp.async)
// ---------------------------------------------------------------------------

__device__ __forceinline__ void ldsm4(uint32_t& r0, uint32_t& r1,
                                      uint32_t& r2, uint32_t& r3, uint32_t a) {
    asm volatile("ldmatrix.sync.aligned.m8n8.x4.shared.b16 {%0,%1,%2,%3}, [%4];"
                 : "=r"(r0), "=r"(r1), "=r"(r2), "=r"(r3) : "r"(a));
}

__device__ __forceinline__ void mma16(float* c, const uint32_t* a, const uint32_t* b) {
    asm volatile(
        "mma.sync.aligned.m16n8k16.row.col.f32.bf16.bf16.f32 "
        "{%0,%1,%2,%3},{%4,%5,%6,%7},{%8,%9},{%0,%1,%2,%3};"
        : "+f"(c[0]), "+f"(c[1]), "+f"(c[2]), "+f"(c[3])
        : "r"(a[0]), "r"(a[1]), "r"(a[2]), "r"(a[3]), "r"(b[0]), "r"(b[1]));
}

__device__ __forceinline__ void cp16(uint32_t s, const void* g) {
    asm volatile("cp.async.cg.shared.global [%0], [%1], 16;" :: "r"(s), "l"(g));
}

#define ASTR 144   // 128B of K (64 bf16) + 16B pad: conflict-free ldmatrix phases

// Fragment loaders. a4: 4 m16-frags (64 rows); a2: 2 m16-frags (32 rows);
// b8: 8 n8-frags (64 rows) loaded pairwise via ldsm.x4.
__device__ __forceinline__ void ldfragsA4(uint32_t (*a)[4], uint32_t Ab, int rowBase,
                                          int kb, int lg, int li) {
#pragma unroll
    for (int mt = 0; mt < 4; mt++) {
        int row = rowBase + mt * 16 + li + (lg & 1) * 8;
        ldsm4(a[mt][0], a[mt][1], a[mt][2], a[mt][3],
              Ab + row * ASTR + kb + (lg >> 1) * 16);
    }
}
__device__ __forceinline__ void ldfragsA2(uint32_t (*a)[4], uint32_t Ab, int rowBase,
                                          int kb, int lg, int li) {
#pragma unroll
    for (int mt = 0; mt < 2; mt++) {
        int row = rowBase + mt * 16 + li + (lg & 1) * 8;
        ldsm4(a[mt][0], a[mt][1], a[mt][2], a[mt][3],
              Ab + row * ASTR + kb + (lg >> 1) * 16);
    }
}
__device__ __forceinline__ void ldfragsB8(uint32_t (*b)[2], uint32_t Bb, int rowBase,
                                          int kb, int lg, int li) {
#pragma unroll
    for (int g = 0; g < 4; g++) {
        int row = rowBase + g * 16 + li + (lg >> 1) * 8;
        uint32_t r0, r1, r2, r3;
        ldsm4(r0, r1, r2, r3, Bb + row * ASTR + kb + (lg & 1) * 16);
        b[2 * g][0] = r0; b[2 * g][1] = r1;
        b[2 * g + 1][0] = r2; b[2 * g + 1][1] = r3;
    }
}

// ---------------------------------------------------------------------------
// Big GEMM (bf16, f32 acc) — EXACT R12 body + griddepcontrol.wait before the
// Pt-reading epilogue (PDL): acc = Xhi[m].Wres[o];
//   y[m][o] = sp[o]*acc + r[o]*Pt[idx[o]][m] + bias[o]
// CTA tile 128x128x64, 128 threads (2x2 warps, warp tile 64x64),
// 3-stage cp.async pipeline, register-double-buffered fragments, 2 CTAs/SM.
// ---------------------------------------------------------------------------

__global__ __launch_bounds__(128, 2)
void gemm_big(const __nv_bfloat16* __restrict__ X, const __nv_bfloat16* __restrict__ W,
              float* __restrict__ Y,
              const int* __restrict__ codes, const float* __restrict__ scales,
              const float* __restrict__ bias, const float* __restrict__ Pt,
              int N, int Mtot)
{
    constexpr int BM = 128, BN = 128;            // rows; row = 64 bf16 = 128B
    constexpr int STAGE = (BM + BN) * ASTR;      // 36864
    constexpr int OFF_ST = 2048;
    extern __shared__ char smem[];
    const int tid = threadIdx.x, lane = tid & 31, wid = tid >> 5;
    const int wm = wid & 1, wn = wid >> 1;       // 2 x 2 warps, warp tile 64x64
    const size_t mBase = (size_t)blockIdx.y * BM;
    const size_t nBase = (size_t)blockIdx.x * BN;
    const uint32_t sb = (uint32_t)__cvta_generic_to_shared(smem);

    // decode per-column params into smem
    int*   idx_s = (int*)smem;
    float* r_s   = (float*)smem + BN;
    float* sp_s  = (float*)smem + 2 * BN;
    float* b_s   = (float*)smem + 3 * BN;
    if (tid < BN) {
        int c = tid;
        int code = codes[nBase + c];
        idx_s[c] = code & 0xFF;
        r_s[c]   = (float)((code >> 8) & 0xFFFF) * (1.0f / 65535.0f);
        sp_s[c]  = scales[nBase + c] * (1.0f / 127.0f);
        b_s[c]   = bias[nBase + c];
    }

    float acc[4][8][4];
#pragma unroll
    for (int i = 0; i < 4; i++)
#pragma unroll
        for (int j = 0; j < 8; j++)
#pragma unroll
            for (int k = 0; k < 4; k++) acc[i][j][k] = 0.f;

    auto fill = [&](int s, int kt) {
        size_t koff = (size_t)kt * 64;           // elements
        uint32_t base = sb + OFF_ST + s * STAGE;
#pragma unroll
        for (int i = 0; i < 16; i++) {
            int id = tid + i * 128;
            bool isB = id >= BM * 8;
            int li2 = isB ? id - BM * 8 : id;
            int r = li2 >> 3, c = li2 & 7;
            const __nv_bfloat16* src =
                (isB ? W + (nBase + r) * (size_t)K_DIM
                     : X + (mBase + r) * (size_t)K_DIM) + koff + c * 8;
            cp16(base + (isB ? BM * ASTR : 0) + r * ASTR + c * 16, src);
        }
        asm volatile("cp.async.commit_group;" ::: "memory");
    };

    fill(0, 0);
    fill(1, 1);
    const int KT = K_DIM / 64;   // 64
    const int lg = lane >> 3, li = lane & 7;
    const int aRow = wm * 64, bRow = wn * 64;

    for (int kt = 0; kt < KT; kt++) {
        int s = kt % 3;
        asm volatile("cp.async.wait_group 1;" ::: "memory");
        __syncthreads();
        if (kt + 2 < KT) fill((kt + 2) % 3, kt + 2);
        else asm volatile("cp.async.commit_group;" ::: "memory");

        uint32_t Ab = sb + OFF_ST + s * STAGE;
        uint32_t Bb = Ab + BM * ASTR;

        uint32_t a[2][4][4], b[2][8][2];
        ldfragsA4(a[0], Ab, aRow, 0, lg, li);
        ldfragsB8(b[0], Bb, bRow, 0, lg, li);
#pragma unroll
        for (int k16 = 0; k16 < 4; k16++) {
            int cur = k16 & 1, nxt = cur ^ 1;
            if (k16 < 3) {
                ldfragsA4(a[nxt], Ab, aRow, (k16 + 1) * 32, lg, li);
                ldfragsB8(b[nxt], Bb, bRow, (k16 + 1) * 32, lg, li);
            }
#pragma unroll
            for (int mt = 0; mt < 4; mt++)
#pragma unroll
                for (int nt = 0; nt < 8; nt++)
                    mma16(acc[mt][nt], a[cur][mt], b[cur][nt]);
        }
    }
    asm volatile("cp.async.wait_group 0;" ::: "memory");
    __syncthreads();

    // PDL: wait for gemm_P's grid (and its memory) before reading Pt.
    asm volatile("griddepcontrol.wait;" ::: "memory");

    // Fused epilogue
    const int t4 = lane >> 2, t2 = (lane & 3) * 2;
#pragma unroll
    for (int mt = 0; mt < 4; mt++) {
#pragma unroll
        for (int p = 0; p < 2; p++) {
            size_t m = mBase + wm * 64 + mt * 16 + t4 + p * 8;
#pragma unroll
            for (int nt = 0; nt < 8; nt++) {
                int nl = wn * 64 + nt * 8 + t2;
                size_t n = nBase + nl;
                float v0 = fmaf(sp_s[nl], acc[mt][nt][2 * p + 0],
                           fmaf(r_s[nl],
                                __ldg(&Pt[(size_t)idx_s[nl] * Mtot + m]), b_s[nl]));
                float v1 = fmaf(sp_s[nl + 1], acc[mt][nt][2 * p + 1],
                           fmaf(r_s[nl + 1],
                                __ldg(&Pt[(size_t)idx_s[nl + 1] * Mtot + m]), b_s[nl + 1]));
                *(float2*)(Y + m * (size_t)N + n) = make_float2(v0, v1);
            }
        }
    }
}

// ---------------------------------------------------------------------------
// P GEMM, FUSED 3-pass (single k-sweep) — EXACT R12 body + early
// griddepcontrol.launch_dependents so gemm_big CTAs backfill free slots:
//   Pt[b][m] = Bhi[b].Xhi[m] + Blo[b].Xhi[m] + Bhi[b].Xlo[m]
// CTA tile 64(basis)x128(tokens), 128 threads (2x2 warps, warp tile 32x64),
// 2-stage pipeline, 2 CTAs/SM. grid = 256 CTAs (one wave).
// ---------------------------------------------------------------------------

__global__ __launch_bounds__(128, 2)
void gemm_P(const __nv_bfloat16* __restrict__ Bh, const __nv_bfloat16* __restrict__ Bl,
            const __nv_bfloat16* __restrict__ Xh, const __nv_bfloat16* __restrict__ Xl,
            float* __restrict__ Pt, int Mtot)
{
    // PDL: allow the dependent gemm_big launch as soon as all P CTAs started.
    asm volatile("griddepcontrol.launch_dependents;" ::: "memory");

    constexpr int BA = 64;                        // basis rows per CTA
    constexpr int BT = 128;                       // token cols per CTA
    constexpr int OFF_AHI = 0;
    constexpr int OFF_ALO = BA * ASTR;            // 9216
    constexpr int OFF_XHI = 2 * BA * ASTR;        // 18432
    constexpr int OFF_XLO = OFF_XHI + BT * ASTR;  // 36864
    constexpr int STAGE   = OFF_XLO + BT * ASTR;  // 55296
    extern __shared__ char smem[];
    const int tid = threadIdx.x, lane = tid & 31, wid = tid >> 5;
    const int wm = wid & 1, wn = wid >> 1;        // warp tile: 32 basis x 64 tokens
    const size_t aBase = (size_t)blockIdx.y * BA; // basis dim
    const size_t nBase = (size_t)blockIdx.x * BT; // token dim
    const uint32_t sb = (uint32_t)__cvta_generic_to_shared(smem);

    float acc[2][8][4];
#pragma unroll
    for (int i = 0; i < 2; i++)
#pragma unroll
        for (int j = 0; j < 8; j++)
#pragma unroll
            for (int k = 0; k < 4; k++) acc[i][j][k] = 0.f;

    auto fill = [&](int s, int kt) {
        size_t koff = (size_t)kt * 64;
        uint32_t base = sb + s * STAGE;
#pragma unroll
        for (int i = 0; i < 24; i++) {
            int id = tid + i * 128;               // 0..3071
            int c = id & 7;
            const __nv_bfloat16* src;
            uint32_t dst;
            if (id < 512) {
                int rr = id >> 3;
                src = Bh + (aBase + rr) * (size_t)K_DIM;
                dst = base + OFF_AHI + rr * ASTR;
            } else if (id < 1024) {
                int rr = (id - 512) >> 3;
                src = Bl + (aBase + rr) * (size_t)K_DIM;
                dst = base + OFF_ALO + rr * ASTR;
            } else if (id < 2048) {
                int rr = (id - 1024) >> 3;
                src = Xh + (nBase + rr) * (size_t)K_DIM;
                dst = base + OFF_XHI + rr * ASTR;
            } else {
                int rr = (id - 2048) >> 3;
                src = Xl + (nBase + rr) * (size_t)K_DIM;
                dst = base + OFF_XLO + rr * ASTR;
            }
            cp16(dst + c * 16, src + koff + c * 8);
        }
        asm volatile("cp.async.commit_group;" ::: "memory");
    };

    fill(0, 0);
    fill(1, 1);
    const int KT = K_DIM / 64;   // 64
    const int lg = lane >> 3, li = lane & 7;
    const int aRow = wm * 32, bRow = wn * 64;

    for (int kt = 0; kt < KT; kt++) {
        int s = kt & 1;
        asm volatile("cp.async.wait_group 1;" ::: "memory");
        __syncthreads();

        uint32_t Ah  = sb + s * STAGE + OFF_AHI;
        uint32_t Al  = sb + s * STAGE + OFF_ALO;
        uint32_t Xhb = sb + s * STAGE + OFF_XHI;
        uint32_t Xlb = sb + s * STAGE + OFF_XLO;

        uint32_t ah[2][2][4], al[2][2][4], xh[2][8][2], xl[2][8][2];
        ldfragsA2(ah[0], Ah, aRow, 0, lg, li);
        ldfragsA2(al[0], Al, aRow, 0, lg, li);
        ldfragsB8(xh[0], Xhb, bRow, 0, lg, li);
        ldfragsB8(xl[0], Xlb, bRow, 0, lg, li);
#pragma unroll
        for (int k16 = 0; k16 < 4; k16++) {
            int cur = k16 & 1, nxt = cur ^ 1;
            if (k16 < 3) {
                int kb = (k16 + 1) * 32;
                ldfragsA2(ah[nxt], Ah, aRow, kb, lg, li);
                ldfragsA2(al[nxt], Al, aRow, kb, lg, li);
                ldfragsB8(xh[nxt], Xhb, bRow, kb, lg, li);
                ldfragsB8(xl[nxt], Xlb, bRow, kb, lg, li);
            }
#pragma unroll
            for (int mt = 0; mt < 2; mt++)
#pragma unroll
                for (int nt = 0; nt < 8; nt++) {
                    mma16(acc[mt][nt], ah[cur][mt], xh[cur][nt]);  // hi.hi
                    mma16(acc[mt][nt], al[cur][mt], xh[cur][nt]);  // lo.hi
                    mma16(acc[mt][nt], ah[cur][mt], xl[cur][nt]);  // hi.lo
                }
        }
        __syncthreads();   // all warps done reading stage s before refilling it
        if (kt + 2 < KT) fill(s, kt + 2);
        else asm volatile("cp.async.commit_group;" ::: "memory");
    }
    asm volatile("cp.async.wait_group 0;" ::: "memory");
    __syncthreads();

    const int t4 = lane >> 2, t2 = (lane & 3) * 2;
#pragma unroll
    for (int mt = 0; mt < 2; mt++) {
#pragma unroll
        for (int p = 0; p < 2; p++) {
            size_t bg = aBase + wm * 32 + mt * 16 + t4 + p * 8;
#pragma unroll
            for (int nt = 0; nt < 8; nt++) {
                size_t mcol = nBase + wn * 64 + nt * 8 + t2;
                *(float2*)(Pt + bg * (size_t)Mtot + mcol) =
                    make_float2(acc[mt][nt][2 * p + 0], acc[mt][nt][2 * p + 1]);
            }
        }
    }
}

// ---------------------------------------------------------------------------
// Launch
// ---------------------------------------------------------------------------

extern "C" void kernel_launch(void* const* d_in, const int* in_sizes, int n_in,
                              void* d_out, int out_size) {
    const float* x      = (const float*)d_in[0];
    const int*   codes  = (const int*)d_in[1];
    const float* basis  = (const float*)d_in[2];
    const int*   residq = (const int*)d_in[3];
    const float* scales = (const float*)d_in[4];
    const float* bias   = (const float*)d_in[5];
    float*       y      = (float*)d_out;

    int N = in_sizes[1];                 // 4096
    int K = in_sizes[2] / NBASIS;        // 4096
    int M = in_sizes[0] / K;             // 8192

    __nv_bfloat16 *Xhi, *Xlo, *Wres, *Bhi, *Blo;
    float* Pt;
    cudaGetSymbolAddress((void**)&Xhi,  g_Xhi);
    cudaGetSymbolAddress((void**)&Xlo,  g_Xlo);
    cudaGetSymbolAddress((void**)&Wres, g_Wres);
    cudaGetSymbolAddress((void**)&Bhi,  g_Bhi);
    cudaGetSymbolAddress((void**)&Blo,  g_Blo);
    cudaGetSymbolAddress((void**)&Pt,   g_Pt);

    constexpr int SMEM_BIG = 2048 + 3 * (128 + 128) * ASTR;    // 112640
    constexpr int SMEM_P   = 2 * (64 + 64 + 128 + 128) * ASTR; // 110592
    cudaFuncSetAttribute(gemm_big, cudaFuncAttributeMaxDynamicSharedMemorySize, SMEM_BIG);
    cudaFuncSetAttribute(gemm_P,   cudaFuncAttributeMaxDynamicSharedMemorySize, SMEM_P);

    // 1) Preprocess: split x and basis into bf16 hi/lo; residual -> exact bf16 ints
    int nx4 = (M * K) / 4;
    prep_x<<<(nx4 + 255) / 256, 256>>>(x, Xhi, Xlo, nx4);
    int nb4 = (NBASIS * K) / 4;
    prep_x<<<(nb4 + 255) / 256, 256>>>(basis, Bhi, Blo, nb4);
    int nw4 = (N * K) / 4;
    prep_w<<<(nw4 + 255) / 256, 256>>>(residq, Wres, nw4);

    // 2) P GEMM (R12 body, triggers dependents early)
    gemm_P<<<dim3(M / 128, NBASIS / 64), 128, SMEM_P>>>(
        Bhi, Blo, Xhi, Xlo, Pt, M);

    // 3) Big GEMM launched with PDL: may begin while gemm_P runs; its
    //    epilogue executes griddepcontrol.wait before reading Pt.
    {
        cudaLaunchConfig_t cfg = {};
        cfg.gridDim  = dim3(N / 128, M / 128);
        cfg.blockDim = dim3(128);
        cfg.dynamicSmemBytes = SMEM_BIG;
        cfg.stream = 0;
        cudaLaunchAttribute attrs[1];
        attrs[0].id = cudaLaunchAttributeProgrammaticStreamSerialization;
        attrs[0].val.programmaticStreamSerializationAllowed = 1;
        cfg.attrs = attrs;
        cfg.numAttrs = 1;
        cudaLaunchKernelEx(&cfg, gemm_big,
                           (const __nv_bfloat16*)Xhi, (const __nv_bfloat16*)Wres,
                           y, codes, scales, bias, (const float*)Pt, N, M);
    }
}